// round 7
// baseline (speedup 1.0000x reference)
#include <cuda_runtime.h>
#include <math.h>
#include <stdint.h>

#define NN 50000
#define NE 1000000
#define NI 200000
#define NB 5000
#define H  128

// ---------------- scratch (device globals; no runtime alloc) ----------------
__device__ float g_A[NN * H];
__device__ float g_B[NN * H];
__device__ float g_L[NN * H];
__device__ float g_R[NN * H];
__device__ int   g_deg[NN];
__device__ int   g_off[NN + 1];
__device__ int   g_cur[NN];
__device__ int   g_csr[NE];

// ---------------- small utility kernels ----------------
__global__ void zero_deg_kernel() {
    int i = blockIdx.x * blockDim.x + threadIdx.x;
    if (i < NN) g_deg[i] = 0;
}

__global__ void count_deg_kernel(const int* __restrict__ dst) {
    int e = blockIdx.x * blockDim.x + threadIdx.x;
    if (e < NE) atomicAdd(&g_deg[dst[e]], 1);
}

__global__ void scan_kernel() {
    __shared__ int part[1024];
    int tid = threadIdx.x;
    const int CH = (NN + 1023) / 1024;
    int base = tid * CH;
    int s = 0;
    for (int c = 0; c < CH; c++) {
        int idx = base + c;
        if (idx < NN) s += g_deg[idx];
    }
    part[tid] = s;
    __syncthreads();
    for (int o = 1; o < 1024; o <<= 1) {
        int v = (tid >= o) ? part[tid - o] : 0;
        __syncthreads();
        part[tid] += v;
        __syncthreads();
    }
    int run = (tid > 0) ? part[tid - 1] : 0;
    for (int c = 0; c < CH; c++) {
        int idx = base + c;
        if (idx < NN) {
            g_off[idx] = run;
            g_cur[idx] = run;
            run += g_deg[idx];
        }
    }
    if (tid == 1023) g_off[NN] = part[1023];
}

__global__ void scatter_kernel(const int* __restrict__ src, const int* __restrict__ dst) {
    int e = blockIdx.x * blockDim.x + threadIdx.x;
    if (e < NE) {
        int d = dst[e];
        int p = atomicAdd(&g_cur[d], 1);
        g_csr[p] = src[e];
    }
}

// ---------------- tf32 helpers ----------------
__device__ __forceinline__ float f2tf(float x) {
    uint32_t u;
    asm("cvt.rna.tf32.f32 %0, %1;" : "=r"(u) : "f"(x));
    return __uint_as_float(u);
}

__device__ __forceinline__ void mma_tf32(float* d, const uint32_t* a, const uint32_t* b) {
    asm volatile(
        "mma.sync.aligned.m16n8k8.row.col.f32.tf32.tf32.f32 "
        "{%0,%1,%2,%3}, {%4,%5,%6,%7}, {%8,%9}, {%0,%1,%2,%3};\n"
        : "+f"(d[0]), "+f"(d[1]), "+f"(d[2]), "+f"(d[3])
        : "r"(a[0]), "r"(a[1]), "r"(a[2]), "r"(a[3]), "r"(b[0]), "r"(b[1]));
}

#define PA 132
#define PB 136
#define MMA_SMEM_BYTES ((128 * PA + 128 * PB) * 4)

// ---- shared staging helpers (512-thread block, 128x128 tiles) ----
template <int MODE_A>
__device__ __forceinline__ void stage_A(float* As, const float* __restrict__ A,
                                        const float* __restrict__ A2,
                                        const int* __restrict__ idx0,
                                        const int* __restrict__ idx1,
                                        int m0, int M, int tid) {
    for (int i = tid; i < 128 * 32; i += 512) {
        int r = i >> 5, q = (i & 31) << 2;
        int gr = m0 + r;
        float4 v = make_float4(0.f, 0.f, 0.f, 0.f);
        if (gr < M) {
            if constexpr (MODE_A == 0) {
                v = *reinterpret_cast<const float4*>(A + (size_t)gr * H + q);
            } else if constexpr (MODE_A == 1) {
                int g = idx0[gr];
                v = *reinterpret_cast<const float4*>(A + (size_t)g * H + q);
            } else if constexpr (MODE_A == 2) {
                int ga = idx0[gr], gb = idx1[gr];
                float4 va = *reinterpret_cast<const float4*>(A + (size_t)ga * H + q);
                float4 vb = *reinterpret_cast<const float4*>(A2 + (size_t)gb * H + q);
                v.x = fmaxf(va.x + vb.x, 0.f);
                v.y = fmaxf(va.y + vb.y, 0.f);
                v.z = fmaxf(va.z + vb.z, 0.f);
                v.w = fmaxf(va.w + vb.w, 0.f);
            } else {
                v = (q < 64) ? *reinterpret_cast<const float4*>(A + (size_t)gr * 64 + q)
                             : *reinterpret_cast<const float4*>(A2 + (size_t)gr * 64 + (q - 64));
            }
        }
        float4 t = make_float4(f2tf(v.x), f2tf(v.y), f2tf(v.z), f2tf(v.w));
        *reinterpret_cast<float4*>(As + r * PA + q) = t;
    }
}

__device__ __forceinline__ void stage_W(float* Bs, const float* __restrict__ W, int tid) {
    for (int i = tid; i < 128 * 32; i += 512) {
        int k = i >> 5, q = (i & 31) << 2;
        float4 v = *reinterpret_cast<const float4*>(W + (size_t)k * 128 + q);
        float4 t = make_float4(f2tf(v.x), f2tf(v.y), f2tf(v.z), f2tf(v.w));
        *reinterpret_cast<float4*>(Bs + k * PB + q) = t;
    }
}

// main-loop compute: warp tile 32x32, acc[2][4][4]
__device__ __forceinline__ void mma_main(const float* As, const float* Bs,
                                         int rA0, int cB0, int g, int tg,
                                         float acc[2][4][4]) {
#pragma unroll
    for (int i = 0; i < 2; i++)
#pragma unroll
        for (int j = 0; j < 4; j++)
#pragma unroll
            for (int c = 0; c < 4; c++) acc[i][j][c] = 0.f;

#pragma unroll 4
    for (int k0 = 0; k0 < 128; k0 += 8) {
        uint32_t af[2][4];
#pragma unroll
        for (int i = 0; i < 2; i++) {
            int rb = rA0 + i * 16;
            af[i][0] = __float_as_uint(As[(rb + g) * PA + k0 + tg]);
            af[i][1] = __float_as_uint(As[(rb + g + 8) * PA + k0 + tg]);
            af[i][2] = __float_as_uint(As[(rb + g) * PA + k0 + tg + 4]);
            af[i][3] = __float_as_uint(As[(rb + g + 8) * PA + k0 + tg + 4]);
        }
        uint32_t bf[4][2];
#pragma unroll
        for (int j = 0; j < 4; j++) {
            int cb = cB0 + j * 8 + g;
            bf[j][0] = __float_as_uint(Bs[(k0 + tg) * PB + cb]);
            bf[j][1] = __float_as_uint(Bs[(k0 + tg + 4) * PB + cb]);
        }
#pragma unroll
        for (int i = 0; i < 2; i++)
#pragma unroll
            for (int j = 0; j < 4; j++) mma_tf32(acc[i][j], af[i], bf[j]);
    }
}

__device__ __forceinline__ void epi_store(float acc[2][4][4], int m0, int M,
                                          int rA0, int cB0, int g, int tg,
                                          const float* __restrict__ bias, int relu,
                                          float* __restrict__ C) {
#pragma unroll
    for (int i = 0; i < 2; i++) {
#pragma unroll
        for (int hh = 0; hh < 2; hh++) {
            int gr = m0 + rA0 + i * 16 + g + hh * 8;
            if (gr < M) {
#pragma unroll
                for (int j = 0; j < 4; j++) {
                    int col = cB0 + j * 8 + 2 * tg;
                    float b0v = bias ? bias[col] : 0.f;
                    float b1v = bias ? bias[col + 1] : 0.f;
                    float2 o;
                    o.x = acc[i][j][hh * 2 + 0] + b0v;
                    o.y = acc[i][j][hh * 2 + 1] + b1v;
                    if (relu) { o.x = fmaxf(o.x, 0.f); o.y = fmaxf(o.y, 0.f); }
                    *reinterpret_cast<float2*>(C + (size_t)gr * 128 + col) = o;
                }
            }
        }
    }
}

// ---------------- single-weight GEMM: C[M,128] = epi(A[M,128] @ W + b) ----------------
// MODE_A: 0=plain, 1=gather idx0, 2=relu(Ha[idx0]+Hb[idx1]), 3=concat(x|emb)
// MODE_E: 0=bias, 1=bias+relu, 2=fused relu->dot(w2)+b2->sigmoid->outv
template <int MODE_A, int MODE_E>
__global__ __launch_bounds__(512, 1)
void mma_gemm(const float* __restrict__ A, const float* __restrict__ A2,
              const int* __restrict__ idx0, const int* __restrict__ idx1,
              int M, const float* __restrict__ W, const float* __restrict__ bias,
              float* __restrict__ C, const float* __restrict__ w2,
              const float* __restrict__ b2, float* __restrict__ outv) {
    extern __shared__ float smem[];
    float* As = smem;
    float* Bs = smem + 128 * PA;

    int tid = threadIdx.x;
    int m0 = blockIdx.x * 128;
    int warp = tid >> 5, lane = tid & 31;
    int wr = warp >> 2, wc = warp & 3;
    int g = lane >> 2, tg = lane & 3;
    int rA0 = wr * 32, cB0 = wc * 32;

    stage_W(Bs, W, tid);
    stage_A<MODE_A>(As, A, A2, idx0, idx1, m0, M, tid);
    __syncthreads();

    float acc[2][4][4];
    mma_main(As, Bs, rA0, cB0, g, tg, acc);

    if constexpr (MODE_E < 2) {
        epi_store(acc, m0, M, rA0, cB0, g, tg, bias, MODE_E == 1, C);
    } else {
        // fused tail: relu(acc + b1) -> As -> dot(w2)+b2 -> sigmoid
        __syncthreads();
#pragma unroll
        for (int i = 0; i < 2; i++) {
#pragma unroll
            for (int hh = 0; hh < 2; hh++) {
                int rr = rA0 + i * 16 + g + hh * 8;
#pragma unroll
                for (int j = 0; j < 4; j++) {
                    int col = cB0 + j * 8 + 2 * tg;
                    float2 o;
                    o.x = fmaxf(acc[i][j][hh * 2 + 0] + bias[col], 0.f);
                    o.y = fmaxf(acc[i][j][hh * 2 + 1] + bias[col + 1], 0.f);
                    *reinterpret_cast<float2*>(As + rr * PA + col) = o;
                }
            }
        }
        __syncthreads();
        float w0 = w2[lane], w1 = w2[lane + 32], wv2 = w2[lane + 64], w3 = w2[lane + 96];
        float bias2 = b2[0];
        for (int rr = warp * 8; rr < warp * 8 + 8; rr++) {
            const float* row = As + rr * PA;
            float p = row[lane] * w0 + row[lane + 32] * w1 + row[lane + 64] * wv2 + row[lane + 96] * w3;
#pragma unroll
            for (int o = 16; o > 0; o >>= 1) p += __shfl_xor_sync(0xffffffffu, p, o);
            int gr = m0 + rr;
            if (lane == 0 && gr < M) outv[gr] = 1.f / (1.f + __expf(-(p + bias2)));
        }
    }
}

// ---------------- dual-weight GEMM: C1 = A@W1+b1, C2 = A@W2+b2 (no relu) ----------------
__global__ __launch_bounds__(512, 1)
void mma_gemm2(const float* __restrict__ A, int M,
               const float* __restrict__ W1, const float* __restrict__ b1v, float* __restrict__ C1,
               const float* __restrict__ W2, const float* __restrict__ b2v, float* __restrict__ C2) {
    extern __shared__ float smem[];
    float* As = smem;
    float* Bs = smem + 128 * PA;

    int tid = threadIdx.x;
    int m0 = blockIdx.x * 128;
    int warp = tid >> 5, lane = tid & 31;
    int wr = warp >> 2, wc = warp & 3;
    int g = lane >> 2, tg = lane & 3;
    int rA0 = wr * 32, cB0 = wc * 32;

    stage_A<0>(As, A, nullptr, nullptr, nullptr, m0, M, tid);
    stage_W(Bs, W1, tid);
    __syncthreads();

    float acc[2][4][4];
    mma_main(As, Bs, rA0, cB0, g, tg, acc);
    epi_store(acc, m0, M, rA0, cB0, g, tg, b1v, 0, C1);

    __syncthreads();               // all warps done reading Bs (pass 1)
    stage_W(Bs, W2, tid);
    __syncthreads();

    mma_main(As, Bs, rA0, cB0, g, tg, acc);
    epi_store(acc, m0, M, rA0, cB0, g, tg, b2v, 0, C2);
}

// ---------------- small SIMT GEMM for final N=64 decoder layer ----------------
__global__ void gemm64_k(const float* __restrict__ A, int M,
                         const float* __restrict__ W, const float* __restrict__ bias,
                         float* __restrict__ C) {
    __shared__ float As[16][68];
    __shared__ float Ws[16][64];
    int tid = threadIdx.x;
    int m0 = blockIdx.x * 64;
    int ty = tid / 8, tx = tid % 8;

    float acc[4][8];
#pragma unroll
    for (int r = 0; r < 4; r++)
#pragma unroll
        for (int c = 0; c < 8; c++) acc[r][c] = 0.f;

    for (int kk = 0; kk < H; kk += 16) {
        for (int i = tid; i < 256; i += 128) {
            int row = i >> 2, kq = (i & 3) * 4;
            float4 v = make_float4(0.f, 0.f, 0.f, 0.f);
            int gr = m0 + row;
            if (gr < M) v = *reinterpret_cast<const float4*>(A + (size_t)gr * H + kk + kq);
            As[kq + 0][row] = v.x;
            As[kq + 1][row] = v.y;
            As[kq + 2][row] = v.z;
            As[kq + 3][row] = v.w;
        }
        for (int i = tid; i < 256; i += 128) {
            int k = i / 16, cq = (i % 16) * 4;
            *reinterpret_cast<float4*>(&Ws[k][cq]) =
                *reinterpret_cast<const float4*>(W + (size_t)(kk + k) * 64 + cq);
        }
        __syncthreads();
#pragma unroll
        for (int k = 0; k < 16; k++) {
            float4 a4 = *reinterpret_cast<const float4*>(&As[k][ty * 4]);
            float a[4] = {a4.x, a4.y, a4.z, a4.w};
            float4 w0 = *reinterpret_cast<const float4*>(&Ws[k][tx * 8]);
            float4 w1 = *reinterpret_cast<const float4*>(&Ws[k][tx * 8 + 4]);
            float w[8] = {w0.x, w0.y, w0.z, w0.w, w1.x, w1.y, w1.z, w1.w};
#pragma unroll
            for (int r = 0; r < 4; r++)
#pragma unroll
                for (int c = 0; c < 8; c++) acc[r][c] = fmaf(a[r], w[c], acc[r][c]);
        }
        __syncthreads();
    }
#pragma unroll
    for (int r = 0; r < 4; r++) {
        int gr = m0 + ty * 4 + r;
        if (gr < M) {
#pragma unroll
            for (int c = 0; c < 8; c += 4) {
                float4 o;
                o.x = acc[r][c + 0] + bias[tx * 8 + c + 0];
                o.y = acc[r][c + 1] + bias[tx * 8 + c + 1];
                o.z = acc[r][c + 2] + bias[tx * 8 + c + 2];
                o.w = acc[r][c + 3] + bias[tx * 8 + c + 3];
                *reinterpret_cast<float4*>(C + (size_t)gr * 64 + tx * 8 + c) = o;
            }
        }
    }
}

// ---------------- GATv2 edge aggregation: one warp per dst, online softmax ----------------
__device__ __forceinline__ float edge_e(float4 l, float4 r, float4 a) {
    float t0 = l.x + r.x; t0 = t0 > 0.f ? t0 : 0.2f * t0;
    float t1 = l.y + r.y; t1 = t1 > 0.f ? t1 : 0.2f * t1;
    float t2 = l.z + r.z; t2 = t2 > 0.f ? t2 : 0.2f * t2;
    float t3 = l.w + r.w; t3 = t3 > 0.f ? t3 : 0.2f * t3;
    float p = t0 * a.x + t1 * a.y + t2 * a.z + t3 * a.w;
#pragma unroll
    for (int o = 16; o > 0; o >>= 1) p += __shfl_xor_sync(0xffffffffu, p, o);
    return p;
}

__global__ void gat_kernel(const float* __restrict__ xl, const float* __restrict__ xr,
                           const float* __restrict__ att, const float* __restrict__ bias,
                           float* __restrict__ hout) {
    int gw = (blockIdx.x * blockDim.x + threadIdx.x) >> 5;
    if (gw >= NN) return;
    int lane = threadIdx.x & 31;

    const float4* XL = reinterpret_cast<const float4*>(xl);
    float4 r4 = reinterpret_cast<const float4*>(xr)[gw * 32 + lane];
    float4 a4 = reinterpret_cast<const float4*>(att)[lane];

    float4 l4 = XL[gw * 32 + lane];
    float m = edge_e(l4, r4, a4);
    float s = 1.f;
    float4 acc = l4;

    int beg = g_off[gw], end = g_off[gw + 1];
    float4 vN;
    if (beg < end) vN = XL[(size_t)g_csr[beg] * 32 + lane];
    for (int j = beg; j < end; j++) {
        float4 v4 = vN;
        int jn = j + 1;
        if (jn < end) vN = XL[(size_t)g_csr[jn] * 32 + lane];  // prefetch next row
        float e = edge_e(v4, r4, a4);
        if (e > m) {  // warp-uniform
            float f = __expf(m - e);
            s = s * f + 1.f;
            acc.x = acc.x * f + v4.x;
            acc.y = acc.y * f + v4.y;
            acc.z = acc.z * f + v4.z;
            acc.w = acc.w * f + v4.w;
            m = e;
        } else {
            float w = __expf(e - m);
            s += w;
            acc.x += v4.x * w;
            acc.y += v4.y * w;
            acc.z += v4.z * w;
            acc.w += v4.w * w;
        }
    }
    float inv = 1.f / s;
    float4 b4 = reinterpret_cast<const float4*>(bias)[lane];
    float4 o;
    o.x = acc.x * inv + b4.x;
    o.y = acc.y * inv + b4.y;
    o.z = acc.z * inv + b4.z;
    o.w = acc.w * inv + b4.w;
    reinterpret_cast<float4*>(hout)[gw * 32 + lane] = o;
}

// ---------------- launcher ----------------
extern "C" void kernel_launch(void* const* d_in, const int* in_sizes, int n_in,
                              void* d_out, int out_size) {
    (void)in_sizes; (void)n_in; (void)out_size;
    const float* x    = (const float*)d_in[0];
    const float* emb  = (const float*)d_in[1];
    const int*   eidx = (const int*)d_in[2];
    const int*   blk  = (const int*)d_in[3];
    const int*   eim  = (const int*)d_in[4];
    const float* encW = (const float*)d_in[5];
    const float* encB = (const float*)d_in[6];
    const float* gWl  = (const float*)d_in[7];
    const float* gbl  = (const float*)d_in[8];
    const float* gWr  = (const float*)d_in[9];
    const float* gbr  = (const float*)d_in[10];
    const float* gatt = (const float*)d_in[11];
    const float* gb   = (const float*)d_in[12];
    const float* eW0  = (const float*)d_in[13];
    const float* eb0  = (const float*)d_in[14];
    const float* eW1  = (const float*)d_in[15];
    const float* eb1  = (const float*)d_in[16];
    const float* eW2  = (const float*)d_in[17];
    const float* eb2  = (const float*)d_in[18];
    const float* nW0  = (const float*)d_in[19];
    const float* nb0  = (const float*)d_in[20];
    const float* nW1  = (const float*)d_in[21];
    const float* nb1  = (const float*)d_in[22];
    const float* nW2  = (const float*)d_in[23];
    const float* nb2  = (const float*)d_in[24];
    float* out = (float*)d_out;

    float *pA, *pB, *pL, *pR;
    cudaGetSymbolAddress((void**)&pA, g_A);
    cudaGetSymbolAddress((void**)&pB, g_B);
    cudaGetSymbolAddress((void**)&pL, g_L);
    cudaGetSymbolAddress((void**)&pR, g_R);

    cudaFuncSetAttribute(mma_gemm<0, 0>, cudaFuncAttributeMaxDynamicSharedMemorySize, MMA_SMEM_BYTES);
    cudaFuncSetAttribute(mma_gemm<0, 1>, cudaFuncAttributeMaxDynamicSharedMemorySize, MMA_SMEM_BYTES);
    cudaFuncSetAttribute(mma_gemm<1, 1>, cudaFuncAttributeMaxDynamicSharedMemorySize, MMA_SMEM_BYTES);
    cudaFuncSetAttribute(mma_gemm<2, 2>, cudaFuncAttributeMaxDynamicSharedMemorySize, MMA_SMEM_BYTES);
    cudaFuncSetAttribute(mma_gemm<3, 1>, cudaFuncAttributeMaxDynamicSharedMemorySize, MMA_SMEM_BYTES);
    cudaFuncSetAttribute(mma_gemm2,      cudaFuncAttributeMaxDynamicSharedMemorySize, MMA_SMEM_BYTES);

    const int* src = eidx;
    const int* dst = eidx + NE;
    const int* im0 = eim;
    const int* im1 = eim + NI;

    // CSR by dst
    zero_deg_kernel<<<(NN + 255) / 256, 256>>>();
    count_deg_kernel<<<(NE + 255) / 256, 256>>>(dst);
    scan_kernel<<<1, 1024>>>();
    scatter_kernel<<<(NE + 255) / 256, 256>>>(src, dst);

    // encoder MLP (layer 1 stages concat(x|emb) directly)
    int gN = (NN + 127) / 128;
    mma_gemm<3, 1><<<gN, 512, MMA_SMEM_BYTES>>>(x, emb, nullptr, nullptr, NN, encW,             encB,         pB, nullptr, nullptr, nullptr);
    mma_gemm<0, 1><<<gN, 512, MMA_SMEM_BYTES>>>(pB, nullptr, nullptr, nullptr, NN, encW + H * H,     encB + H,     pL, nullptr, nullptr, nullptr);
    mma_gemm<0, 0><<<gN, 512, MMA_SMEM_BYTES>>>(pL, nullptr, nullptr, nullptr, NN, encW + 2 * H * H, encB + 2 * H, pA, nullptr, nullptr, nullptr);

    // 3 GATv2 layers (dual-weight GEMM: xl and xr from one A staging)
    float* hcur = pA;
    float* hnxt = pB;
    for (int i = 0; i < 3; i++) {
        mma_gemm2<<<gN, 512, MMA_SMEM_BYTES>>>(hcur, NN,
                                               gWl + i * H * H, gbl + i * H, pL,
                                               gWr + i * H * H, gbr + i * H, pR);
        gat_kernel<<<(NN * 32 + 255) / 256, 256>>>(pL, pR, gatt + i * H, gb + i * H, hnxt);
        float* t = hcur; hcur = hnxt; hnxt = t;
    }
    // hcur == pB after 3 layers

    // edge decoder: Ha/Hb from one staging of h
    mma_gemm2<<<gN, 512, MMA_SMEM_BYTES>>>(hcur, NN, eW0, eb0, pL, eW0 + H * H, nullptr, pR);
    // fused: relu(Ha[s]+Hb[d]) @ W1 + b1 -> relu -> dot W2 + b2 -> sigmoid
    mma_gemm<2, 2><<<(NI + 127) / 128, 512, MMA_SMEM_BYTES>>>(pL, pR, im0, im1, NI, eW1, eb1, nullptr, eW2, eb2, out + NB * 64);

    // node decoder on block_index rows
    int gB = (NB + 127) / 128;
    mma_gemm<1, 1><<<gB, 512, MMA_SMEM_BYTES>>>(hcur, nullptr, blk, nullptr, NB, nW0, nb0, pL, nullptr, nullptr, nullptr);
    mma_gemm<0, 1><<<gB, 512, MMA_SMEM_BYTES>>>(pL, nullptr, nullptr, nullptr, NB, nW1, nb1, pR, nullptr, nullptr, nullptr);
    gemm64_k<<<(NB + 63) / 64, 128>>>(pR, NB, nW2, nb2, out);
}

// round 8
// speedup vs baseline: 1.3728x; 1.3728x over previous
#include <cuda_runtime.h>
#include <math.h>
#include <stdint.h>

#define NN 50000
#define NE 1000000
#define NI 200000
#define NB 5000
#define H  128

// ---------------- scratch (device globals; no runtime alloc) ----------------
__device__ float g_A[NN * H];
__device__ float g_B[NN * H];
__device__ float g_L[NN * H];
__device__ float g_R[NN * H];
__device__ int   g_deg[NN];
__device__ int   g_off[NN + 1];
__device__ int   g_cur[NN];
__device__ int   g_csr[NE];

// ---------------- small utility kernels ----------------
__global__ void zero_deg_kernel() {
    int i = blockIdx.x * blockDim.x + threadIdx.x;
    if (i < NN) g_deg[i] = 0;
}

__global__ void count_deg_kernel(const int* __restrict__ dst) {
    int e = blockIdx.x * blockDim.x + threadIdx.x;
    if (e < NE) atomicAdd(&g_deg[dst[e]], 1);
}

__global__ void scan_kernel() {
    __shared__ int part[1024];
    int tid = threadIdx.x;
    const int CH = (NN + 1023) / 1024;
    int base = tid * CH;
    int s = 0;
    for (int c = 0; c < CH; c++) {
        int idx = base + c;
        if (idx < NN) s += g_deg[idx];
    }
    part[tid] = s;
    __syncthreads();
    for (int o = 1; o < 1024; o <<= 1) {
        int v = (tid >= o) ? part[tid - o] : 0;
        __syncthreads();
        part[tid] += v;
        __syncthreads();
    }
    int run = (tid > 0) ? part[tid - 1] : 0;
    for (int c = 0; c < CH; c++) {
        int idx = base + c;
        if (idx < NN) {
            g_off[idx] = run;
            g_cur[idx] = run;
            run += g_deg[idx];
        }
    }
    if (tid == 1023) g_off[NN] = part[1023];
}

__global__ void scatter_kernel(const int* __restrict__ src, const int* __restrict__ dst) {
    int e = blockIdx.x * blockDim.x + threadIdx.x;
    if (e < NE) {
        int d = dst[e];
        int p = atomicAdd(&g_cur[d], 1);
        g_csr[p] = src[e];
    }
}

// ---------------- tf32 helpers ----------------
__device__ __forceinline__ float f2tf(float x) {
    uint32_t u;
    asm("cvt.rna.tf32.f32 %0, %1;" : "=r"(u) : "f"(x));
    return __uint_as_float(u);
}

__device__ __forceinline__ void mma_tf32(float* d, const uint32_t* a, const uint32_t* b) {
    asm volatile(
        "mma.sync.aligned.m16n8k8.row.col.f32.tf32.tf32.f32 "
        "{%0,%1,%2,%3}, {%4,%5,%6,%7}, {%8,%9}, {%0,%1,%2,%3};\n"
        : "+f"(d[0]), "+f"(d[1]), "+f"(d[2]), "+f"(d[3])
        : "r"(a[0]), "r"(a[1]), "r"(a[2]), "r"(a[3]), "r"(b[0]), "r"(b[1]));
}

// SMEM layout: fragment-packed.
//   Af[rbi(8)][k0i(16)][lane(32)][4]  floats = 16384 f = 64KB
//   Bf[k0i(16)][cbi(16)][lane(32)][2] floats = 16384 f = 64KB
#define AF_FLOATS 16384
#define MMA_SMEM_BYTES (2 * 16384 * 4)
#define CS_P 132   // pitch for fused-tail scratch (overlays smem)

// ---------------- fragment-packed tf32 GEMM: C[M,128] = epi(A[M,128] @ W + b) --------
// MODE_A: 0=plain, 1=gather idx0, 2=relu(Ha[idx0]+Hb[idx1]), 3=concat(x[64]|emb[64])
// MODE_E: 0=bias, 1=bias+relu, 2=fused relu->dot(w2)+b2->sigmoid->outv
template <int MODE_A, int MODE_E>
__global__ __launch_bounds__(256, 1)
void mma_gemm(const float* __restrict__ A, const float* __restrict__ A2,
              const int* __restrict__ idx0, const int* __restrict__ idx1,
              int M, const float* __restrict__ W, const float* __restrict__ bias,
              float* __restrict__ C, const float* __restrict__ w2,
              const float* __restrict__ b2, float* __restrict__ outv) {
    extern __shared__ float smem[];
    float* Af = smem;
    float* Bf = smem + AF_FLOATS;

    int tid = threadIdx.x;
    int m0 = blockIdx.x * 128;
    int warp = tid >> 5, lane = tid & 31;
    int g = lane >> 2, tg = lane & 3;

    // ---- stage W fragments: Bf[k0i][cbi][lane] = {W[k0+tg][c], W[k0+4+tg][c]} ----
#pragma unroll
    for (int h = 0; h < 2; h++) {
        int cbi = warp * 2 + h;
        int c = cbi * 8 + g;
#pragma unroll 4
        for (int k0i = 0; k0i < 16; k0i++) {
            int k = k0i * 8 + tg;
            float2 t;
            t.x = f2tf(W[(size_t)k * 128 + c]);
            t.y = f2tf(W[(size_t)(k + 4) * 128 + c]);
            *reinterpret_cast<float2*>(Bf + ((k0i * 16 + cbi) * 32 + lane) * 2) = t;
        }
    }

    // ---- stage A fragments: Af[rbi][k0i][lane] = {a(r1,k), a(r2,k), a(r1,k+4), a(r2,k+4)} ----
    {
        int r1 = m0 + warp * 16 + g;    // rbi == warp
        int r2 = r1 + 8;
        bool ok1 = r1 < M, ok2 = r2 < M;

        const float* p1 = nullptr; const float* p2 = nullptr;
        const float* q1 = nullptr; const float* q2 = nullptr;
        if constexpr (MODE_A == 0) {
            p1 = ok1 ? A + (size_t)r1 * H : nullptr;
            p2 = ok2 ? A + (size_t)r2 * H : nullptr;
        } else if constexpr (MODE_A == 1) {
            p1 = ok1 ? A + (size_t)idx0[r1] * H : nullptr;
            p2 = ok2 ? A + (size_t)idx0[r2] * H : nullptr;
        } else if constexpr (MODE_A == 2) {
            if (ok1) { p1 = A + (size_t)idx0[r1] * H; q1 = A2 + (size_t)idx1[r1] * H; }
            if (ok2) { p2 = A + (size_t)idx0[r2] * H; q2 = A2 + (size_t)idx1[r2] * H; }
        }
#pragma unroll 4
        for (int k0i = 0; k0i < 16; k0i++) {
            int k = k0i * 8 + tg;
            float4 v = make_float4(0.f, 0.f, 0.f, 0.f);
            if constexpr (MODE_A == 0 || MODE_A == 1) {
                if (p1) { v.x = p1[k]; v.z = p1[k + 4]; }
                if (p2) { v.y = p2[k]; v.w = p2[k + 4]; }
            } else if constexpr (MODE_A == 2) {
                if (p1) {
                    v.x = fmaxf(p1[k] + q1[k], 0.f);
                    v.z = fmaxf(p1[k + 4] + q1[k + 4], 0.f);
                }
                if (p2) {
                    v.y = fmaxf(p2[k] + q2[k], 0.f);
                    v.w = fmaxf(p2[k + 4] + q2[k + 4], 0.f);
                }
            } else {  // concat(x|emb): k<64 -> x, else emb (k0i splits cleanly at 8)
                const float* b1 = (k0i < 8) ? (A + (size_t)r1 * 64) : (A2 + (size_t)r1 * 64 - 64);
                const float* b2p = (k0i < 8) ? (A + (size_t)r2 * 64) : (A2 + (size_t)r2 * 64 - 64);
                if (ok1) { v.x = b1[k]; v.z = b1[k + 4]; }
                if (ok2) { v.y = b2p[k]; v.w = b2p[k + 4]; }
            }
            float4 t = make_float4(f2tf(v.x), f2tf(v.y), f2tf(v.z), f2tf(v.w));
            *reinterpret_cast<float4*>(Af + ((warp * 16 + k0i) * 32 + lane) * 4) = t;
        }
    }
    __syncthreads();

    // ---- mainloop: warp tile 32x64, 1 LDS.128 per A-frag, 1 LDS.64 per B-frag ----
    int wr = warp >> 1, wc = warp & 1;
    int rA0 = wr * 32, cB0 = wc * 64;

    float acc[2][8][4];
#pragma unroll
    for (int i = 0; i < 2; i++)
#pragma unroll
        for (int j = 0; j < 8; j++)
#pragma unroll
            for (int c = 0; c < 4; c++) acc[i][j][c] = 0.f;

#pragma unroll 4
    for (int k0i = 0; k0i < 16; k0i++) {
        uint32_t af[2][4];
#pragma unroll
        for (int i = 0; i < 2; i++) {
            uint4 a = *reinterpret_cast<const uint4*>(
                Af + (((wr * 2 + i) * 16 + k0i) * 32 + lane) * 4);
            af[i][0] = a.x; af[i][1] = a.y; af[i][2] = a.z; af[i][3] = a.w;
        }
        uint32_t bf[8][2];
#pragma unroll
        for (int j = 0; j < 8; j++) {
            uint2 b = *reinterpret_cast<const uint2*>(
                Bf + ((k0i * 16 + wc * 8 + j) * 32 + lane) * 2);
            bf[j][0] = b.x; bf[j][1] = b.y;
        }
#pragma unroll
        for (int i = 0; i < 2; i++)
#pragma unroll
            for (int j = 0; j < 8; j++) mma_tf32(acc[i][j], af[i], bf[j]);
    }

    if constexpr (MODE_E < 2) {
#pragma unroll
        for (int i = 0; i < 2; i++) {
#pragma unroll
            for (int hh = 0; hh < 2; hh++) {
                int gr = m0 + rA0 + i * 16 + g + hh * 8;
                if (gr < M) {
#pragma unroll
                    for (int j = 0; j < 8; j++) {
                        int col = cB0 + j * 8 + 2 * tg;
                        float b0v = bias ? bias[col] : 0.f;
                        float b1v = bias ? bias[col + 1] : 0.f;
                        float2 o;
                        o.x = acc[i][j][hh * 2 + 0] + b0v;
                        o.y = acc[i][j][hh * 2 + 1] + b1v;
                        if (MODE_E == 1) { o.x = fmaxf(o.x, 0.f); o.y = fmaxf(o.y, 0.f); }
                        *reinterpret_cast<float2*>(C + (size_t)gr * 128 + col) = o;
                    }
                }
            }
        }
    } else {
        // fused tail: relu(acc + b1) -> Cs(smem) -> dot(w2)+b2 -> sigmoid
        __syncthreads();  // fragments consumed; overlay smem as Cs[128][CS_P]
        float* Cs = smem;
#pragma unroll
        for (int i = 0; i < 2; i++) {
#pragma unroll
            for (int hh = 0; hh < 2; hh++) {
                int rr = rA0 + i * 16 + g + hh * 8;
#pragma unroll
                for (int j = 0; j < 8; j++) {
                    int col = cB0 + j * 8 + 2 * tg;
                    float2 o;
                    o.x = fmaxf(acc[i][j][hh * 2 + 0] + bias[col], 0.f);
                    o.y = fmaxf(acc[i][j][hh * 2 + 1] + bias[col + 1], 0.f);
                    *reinterpret_cast<float2*>(Cs + rr * CS_P + col) = o;
                }
            }
        }
        __syncthreads();
        float4 wv = *reinterpret_cast<const float4*>(w2 + lane * 4);
        float bias2 = b2[0];
        for (int rr = warp * 16; rr < warp * 16 + 16; rr++) {
            float4 c4 = *reinterpret_cast<const float4*>(Cs + rr * CS_P + lane * 4);
            float p = c4.x * wv.x + c4.y * wv.y + c4.z * wv.z + c4.w * wv.w;
#pragma unroll
            for (int o = 16; o > 0; o >>= 1) p += __shfl_xor_sync(0xffffffffu, p, o);
            int gr = m0 + rr;
            if (lane == 0 && gr < M) outv[gr] = 1.f / (1.f + __expf(-(p + bias2)));
        }
    }
}

// ---------------- small SIMT GEMM for final N=64 decoder layer ----------------
__global__ void gemm64_k(const float* __restrict__ A, int M,
                         const float* __restrict__ W, const float* __restrict__ bias,
                         float* __restrict__ C) {
    __shared__ float As[16][68];
    __shared__ float Ws[16][64];
    int tid = threadIdx.x;
    int m0 = blockIdx.x * 64;
    int ty = tid / 8, tx = tid % 8;

    float acc[4][8];
#pragma unroll
    for (int r = 0; r < 4; r++)
#pragma unroll
        for (int c = 0; c < 8; c++) acc[r][c] = 0.f;

    for (int kk = 0; kk < H; kk += 16) {
        for (int i = tid; i < 256; i += 128) {
            int row = i >> 2, kq = (i & 3) * 4;
            float4 v = make_float4(0.f, 0.f, 0.f, 0.f);
            int gr = m0 + row;
            if (gr < M) v = *reinterpret_cast<const float4*>(A + (size_t)gr * H + kk + kq);
            As[kq + 0][row] = v.x;
            As[kq + 1][row] = v.y;
            As[kq + 2][row] = v.z;
            As[kq + 3][row] = v.w;
        }
        for (int i = tid; i < 256; i += 128) {
            int k = i / 16, cq = (i % 16) * 4;
            *reinterpret_cast<float4*>(&Ws[k][cq]) =
                *reinterpret_cast<const float4*>(W + (size_t)(kk + k) * 64 + cq);
        }
        __syncthreads();
#pragma unroll
        for (int k = 0; k < 16; k++) {
            float4 a4 = *reinterpret_cast<const float4*>(&As[k][ty * 4]);
            float a[4] = {a4.x, a4.y, a4.z, a4.w};
            float4 w0 = *reinterpret_cast<const float4*>(&Ws[k][tx * 8]);
            float4 w1 = *reinterpret_cast<const float4*>(&Ws[k][tx * 8 + 4]);
            float w[8] = {w0.x, w0.y, w0.z, w0.w, w1.x, w1.y, w1.z, w1.w};
#pragma unroll
            for (int r = 0; r < 4; r++)
#pragma unroll
                for (int c = 0; c < 8; c++) acc[r][c] = fmaf(a[r], w[c], acc[r][c]);
        }
        __syncthreads();
    }
#pragma unroll
    for (int r = 0; r < 4; r++) {
        int gr = m0 + ty * 4 + r;
        if (gr < M) {
#pragma unroll
            for (int c = 0; c < 8; c += 4) {
                float4 o;
                o.x = acc[r][c + 0] + bias[tx * 8 + c + 0];
                o.y = acc[r][c + 1] + bias[tx * 8 + c + 1];
                o.z = acc[r][c + 2] + bias[tx * 8 + c + 2];
                o.w = acc[r][c + 3] + bias[tx * 8 + c + 3];
                *reinterpret_cast<float4*>(C + (size_t)gr * 64 + tx * 8 + c) = o;
            }
        }
    }
}

// ---------------- GATv2 edge aggregation: one warp per dst, online softmax ----------------
__device__ __forceinline__ float edge_e(float4 l, float4 r, float4 a) {
    float t0 = l.x + r.x; t0 = t0 > 0.f ? t0 : 0.2f * t0;
    float t1 = l.y + r.y; t1 = t1 > 0.f ? t1 : 0.2f * t1;
    float t2 = l.z + r.z; t2 = t2 > 0.f ? t2 : 0.2f * t2;
    float t3 = l.w + r.w; t3 = t3 > 0.f ? t3 : 0.2f * t3;
    float p = t0 * a.x + t1 * a.y + t2 * a.z + t3 * a.w;
#pragma unroll
    for (int o = 16; o > 0; o >>= 1) p += __shfl_xor_sync(0xffffffffu, p, o);
    return p;
}

__global__ void gat_kernel(const float* __restrict__ xl, const float* __restrict__ xr,
                           const float* __restrict__ att, const float* __restrict__ bias,
                           float* __restrict__ hout) {
    int gw = (blockIdx.x * blockDim.x + threadIdx.x) >> 5;
    if (gw >= NN) return;
    int lane = threadIdx.x & 31;

    const float4* XL = reinterpret_cast<const float4*>(xl);
    float4 r4 = reinterpret_cast<const float4*>(xr)[gw * 32 + lane];
    float4 a4 = reinterpret_cast<const float4*>(att)[lane];

    float4 l4 = XL[gw * 32 + lane];
    float m = edge_e(l4, r4, a4);
    float s = 1.f;
    float4 acc = l4;

    int beg = g_off[gw], end = g_off[gw + 1];
    float4 vN;
    if (beg < end) vN = XL[(size_t)g_csr[beg] * 32 + lane];
    for (int j = beg; j < end; j++) {
        float4 v4 = vN;
        int jn = j + 1;
        if (jn < end) vN = XL[(size_t)g_csr[jn] * 32 + lane];  // prefetch next row
        float e = edge_e(v4, r4, a4);
        if (e > m) {  // warp-uniform
            float f = __expf(m - e);
            s = s * f + 1.f;
            acc.x = acc.x * f + v4.x;
            acc.y = acc.y * f + v4.y;
            acc.z = acc.z * f + v4.z;
            acc.w = acc.w * f + v4.w;
            m = e;
        } else {
            float w = __expf(e - m);
            s += w;
            acc.x += v4.x * w;
            acc.y += v4.y * w;
            acc.z += v4.z * w;
            acc.w += v4.w * w;
        }
    }
    float inv = 1.f / s;
    float4 b4 = reinterpret_cast<const float4*>(bias)[lane];
    float4 o;
    o.x = acc.x * inv + b4.x;
    o.y = acc.y * inv + b4.y;
    o.z = acc.z * inv + b4.z;
    o.w = acc.w * inv + b4.w;
    reinterpret_cast<float4*>(hout)[gw * 32 + lane] = o;
}

// ---------------- launcher ----------------
extern "C" void kernel_launch(void* const* d_in, const int* in_sizes, int n_in,
                              void* d_out, int out_size) {
    (void)in_sizes; (void)n_in; (void)out_size;
    const float* x    = (const float*)d_in[0];
    const float* emb  = (const float*)d_in[1];
    const int*   eidx = (const int*)d_in[2];
    const int*   blk  = (const int*)d_in[3];
    const int*   eim  = (const int*)d_in[4];
    const float* encW = (const float*)d_in[5];
    const float* encB = (const float*)d_in[6];
    const float* gWl  = (const float*)d_in[7];
    const float* gbl  = (const float*)d_in[8];
    const float* gWr  = (const float*)d_in[9];
    const float* gbr  = (const float*)d_in[10];
    const float* gatt = (const float*)d_in[11];
    const float* gb   = (const float*)d_in[12];
    const float* eW0  = (const float*)d_in[13];
    const float* eb0  = (const float*)d_in[14];
    const float* eW1  = (const float*)d_in[15];
    const float* eb1  = (const float*)d_in[16];
    const float* eW2  = (const float*)d_in[17];
    const float* eb2  = (const float*)d_in[18];
    const float* nW0  = (const float*)d_in[19];
    const float* nb0  = (const float*)d_in[20];
    const float* nW1  = (const float*)d_in[21];
    const float* nb1  = (const float*)d_in[22];
    const float* nW2  = (const float*)d_in[23];
    const float* nb2  = (const float*)d_in[24];
    float* out = (float*)d_out;

    float *pA, *pB, *pL, *pR;
    cudaGetSymbolAddress((void**)&pA, g_A);
    cudaGetSymbolAddress((void**)&pB, g_B);
    cudaGetSymbolAddress((void**)&pL, g_L);
    cudaGetSymbolAddress((void**)&pR, g_R);

    cudaFuncSetAttribute(mma_gemm<0, 0>, cudaFuncAttributeMaxDynamicSharedMemorySize, MMA_SMEM_BYTES);
    cudaFuncSetAttribute(mma_gemm<0, 1>, cudaFuncAttributeMaxDynamicSharedMemorySize, MMA_SMEM_BYTES);
    cudaFuncSetAttribute(mma_gemm<1, 1>, cudaFuncAttributeMaxDynamicSharedMemorySize, MMA_SMEM_BYTES);
    cudaFuncSetAttribute(mma_gemm<2, 2>, cudaFuncAttributeMaxDynamicSharedMemorySize, MMA_SMEM_BYTES);
    cudaFuncSetAttribute(mma_gemm<3, 1>, cudaFuncAttributeMaxDynamicSharedMemorySize, MMA_SMEM_BYTES);

    const int* src = eidx;
    const int* dst = eidx + NE;
    const int* im0 = eim;
    const int* im1 = eim + NI;

    // CSR by dst
    zero_deg_kernel<<<(NN + 255) / 256, 256>>>();
    count_deg_kernel<<<(NE + 255) / 256, 256>>>(dst);
    scan_kernel<<<1, 1024>>>();
    scatter_kernel<<<(NE + 255) / 256, 256>>>(src, dst);

    // encoder MLP (layer 1 stages concat(x|emb) directly)
    int gN = (NN + 127) / 128;
    mma_gemm<3, 1><<<gN, 256, MMA_SMEM_BYTES>>>(x, emb, nullptr, nullptr, NN, encW,             encB,         pB, nullptr, nullptr, nullptr);
    mma_gemm<0, 1><<<gN, 256, MMA_SMEM_BYTES>>>(pB, nullptr, nullptr, nullptr, NN, encW + H * H,     encB + H,     pL, nullptr, nullptr, nullptr);
    mma_gemm<0, 0><<<gN, 256, MMA_SMEM_BYTES>>>(pL, nullptr, nullptr, nullptr, NN, encW + 2 * H * H, encB + 2 * H, pA, nullptr, nullptr, nullptr);

    // 3 GATv2 layers
    float* hcur = pA;
    float* hnxt = pB;
    for (int i = 0; i < 3; i++) {
        mma_gemm<0, 0><<<gN, 256, MMA_SMEM_BYTES>>>(hcur, nullptr, nullptr, nullptr, NN, gWl + i * H * H, gbl + i * H, pL, nullptr, nullptr, nullptr);
        mma_gemm<0, 0><<<gN, 256, MMA_SMEM_BYTES>>>(hcur, nullptr, nullptr, nullptr, NN, gWr + i * H * H, gbr + i * H, pR, nullptr, nullptr, nullptr);
        gat_kernel<<<(NN * 32 + 255) / 256, 256>>>(pL, pR, gatt + i * H, gb + i * H, hnxt);
        float* t = hcur; hcur = hnxt; hnxt = t;
    }
    // hcur == pB after 3 layers

    // edge decoder: split W0 into src/dst halves, node-side projections once
    mma_gemm<0, 0><<<gN, 256, MMA_SMEM_BYTES>>>(hcur, nullptr, nullptr, nullptr, NN, eW0,         eb0,     pL, nullptr, nullptr, nullptr);  // Ha
    mma_gemm<0, 0><<<gN, 256, MMA_SMEM_BYTES>>>(hcur, nullptr, nullptr, nullptr, NN, eW0 + H * H, nullptr, pR, nullptr, nullptr, nullptr);  // Hb
    // fused: relu(Ha[s]+Hb[d]) @ W1 + b1 -> relu -> dot W2 + b2 -> sigmoid
    mma_gemm<2, 2><<<(NI + 127) / 128, 256, MMA_SMEM_BYTES>>>(pL, pR, im0, im1, NI, eW1, eb1, nullptr, eW2, eb2, out + NB * 64);

    // node decoder on block_index rows
    int gB = (NB + 127) / 128;
    mma_gemm<1, 1><<<gB, 256, MMA_SMEM_BYTES>>>(hcur, nullptr, blk, nullptr, NB, nW0, nb0, pL, nullptr, nullptr, nullptr);
    mma_gemm<0, 1><<<gB, 256, MMA_SMEM_BYTES>>>(pL, nullptr, nullptr, nullptr, NB, nW1, nb1, pR, nullptr, nullptr, nullptr);
    gemm64_k<<<(NB + 63) / 64, 128>>>(pR, NB, nW2, nb2, out);
}